// round 17
// baseline (speedup 1.0000x reference)
#include <cuda_runtime.h>
#include <cstdint>

// Output: (BATCH=256, SEQ=512, DIM=64) fp32.
// inputs: (256,512) fp32; tables: (3,100000,64) fp32; table_ids: (512) int32.
//
// Transaction-count halving: 256-bit loads AND 256-bit stores (v8.b32).
// Each thread owns 4 x 32B slots (pair of float4s): 4 LDG.256 back-to-back
// (forced MLP=4 x 32B = same bytes in flight as 8 x 16B) + 4 STG.256.
// No cache hints (all tested neutral). 256 threads, 128 rows/block.

#define BATCH 256
#define SEQ   512
#define DIM   64
#define VOCAB 100000
#define ROWS_PER_BLK 128
#define THREADS 256
#define U 4                        // 128 rows * 8 pairs / 256 threads

__global__ void __launch_bounds__(THREADS)
emb_gather_kernel(const float* __restrict__ inputs,
                  const float* __restrict__ tables,
                  const int*   __restrict__ table_ids,
                  float4*      __restrict__ out)
{
    __shared__ int   s_off[ROWS_PER_BLK];  // float-index into tables, or -1
    __shared__ float s_val[ROWS_PER_BLK];

    const int tid  = threadIdx.x;
    const int row0 = blockIdx.x * ROWS_PER_BLK;

    // ---- Phase 1: per-row descriptors ----
    if (tid < ROWS_PER_BLK) {
        int row = row0 + tid;
        int s   = row & (SEQ - 1);
        float v = __ldg(&inputs[row]);
        int  tb = __ldg(&table_ids[s]);
        s_val[tid] = v;
        s_off[tid] = (tb >= 0) ? (tb * VOCAB + (int)v) * DIM : -1;  // float idx
    }
    __syncthreads();

    int   off[U];
    float val[U];
    unsigned long long addr[U];
    #pragma unroll
    for (int k = 0; k < U; k++) {
        int j     = k * THREADS + tid;   // 32B pair slot: [0, 1024)
        int rl    = j >> 3;              // local row
        int lane8 = j & 7;               // which 32B chunk of the 256B row
        off[k] = s_off[rl];
        val[k] = s_val[rl];
        int safe = off[k] >= 0 ? off[k] : 0;   // numeric rows -> table row 0
        addr[k] = (unsigned long long)tables
                + ((unsigned long long)(unsigned)(safe + lane8 * 8) << 2);
    }

    // ---- 4 x LDG.256 back-to-back ----
    float x[32];
    asm volatile(
        "ld.global.nc.v8.f32 {%0,%1,%2,%3,%4,%5,%6,%7},         [%32];\n\t"
        "ld.global.nc.v8.f32 {%8,%9,%10,%11,%12,%13,%14,%15},   [%33];\n\t"
        "ld.global.nc.v8.f32 {%16,%17,%18,%19,%20,%21,%22,%23}, [%34];\n\t"
        "ld.global.nc.v8.f32 {%24,%25,%26,%27,%28,%29,%30,%31}, [%35];\n\t"
        : "=f"(x[0]),  "=f"(x[1]),  "=f"(x[2]),  "=f"(x[3]),
          "=f"(x[4]),  "=f"(x[5]),  "=f"(x[6]),  "=f"(x[7]),
          "=f"(x[8]),  "=f"(x[9]),  "=f"(x[10]), "=f"(x[11]),
          "=f"(x[12]), "=f"(x[13]), "=f"(x[14]), "=f"(x[15]),
          "=f"(x[16]), "=f"(x[17]), "=f"(x[18]), "=f"(x[19]),
          "=f"(x[20]), "=f"(x[21]), "=f"(x[22]), "=f"(x[23]),
          "=f"(x[24]), "=f"(x[25]), "=f"(x[26]), "=f"(x[27]),
          "=f"(x[28]), "=f"(x[29]), "=f"(x[30]), "=f"(x[31])
        : "l"(addr[0]), "l"(addr[1]), "l"(addr[2]), "l"(addr[3]));

    // ---- select + 4 x STG.256 ----
    float* obase = (float*)(out + (size_t)row0 * (DIM / 4));
    #pragma unroll
    for (int k = 0; k < U; k++) {
        int j = k * THREADS + tid;
        float y[8];
        if (off[k] >= 0) {
            #pragma unroll
            for (int e = 0; e < 8; e++) y[e] = x[8*k + e];
        } else {
            #pragma unroll
            for (int e = 0; e < 8; e++) y[e] = val[k];
        }
        float* dst = obase + (size_t)j * 8;
        asm volatile(
            "st.global.v8.f32 [%0], {%1,%2,%3,%4,%5,%6,%7,%8};"
            :: "l"(dst),
               "f"(y[0]), "f"(y[1]), "f"(y[2]), "f"(y[3]),
               "f"(y[4]), "f"(y[5]), "f"(y[6]), "f"(y[7])
            : "memory");
    }
}

extern "C" void kernel_launch(void* const* d_in, const int* in_sizes, int n_in,
                              void* d_out, int out_size)
{
    const float* inputs    = (const float*)d_in[0];
    const float* tables    = (const float*)d_in[1];
    const int*   table_ids = (const int*)d_in[2];
    float4*      out       = (float4*)d_out;

    int blocks = (BATCH * SEQ) / ROWS_PER_BLK;   // 1024
    emb_gather_kernel<<<blocks, THREADS>>>(inputs, tables, table_ids, out);
}